// round 1
// baseline (speedup 1.0000x reference)
#include <cuda_runtime.h>
#include <math.h>

#define IMG_H 192
#define IMG_W 192
#define TANFOVX 0.5f
#define TANFOVY 0.5f
#define SCALE_MOD 1.0f
#define NEAR_Z 0.2f
#define ALPHA_MIN (1.0f / 255.0f)
#define T_EPS 1.0e-4f
#define PMAX 1024

// Sorted per-gaussian params (SoA), produced by preprocess, consumed by render.
__device__ float g_px[PMAX], g_py[PMAX];
__device__ float g_cA[PMAX], g_cB[PMAX], g_cC[PMAX];
__device__ float g_op[PMAX], g_thr[PMAX];
__device__ float g_cr[PMAX], g_cg[PMAX], g_cb[PMAX];

__global__ void preprocess_kernel(const float* __restrict__ means3D,
                                  const float* __restrict__ opac,
                                  const float* __restrict__ colors,
                                  const float* __restrict__ scales,
                                  const float* __restrict__ rots,
                                  const float* __restrict__ vm,
                                  const float* __restrict__ pm,
                                  float* __restrict__ out_radii,
                                  int P) {
    int i = threadIdx.x;
    __shared__ float s_depth[PMAX];

    float depth = 3.4e38f;
    float pxp = 0.f, pyp = 0.f, conA = 0.f, conB = 0.f, conC = 0.f;
    float op = 0.f, thr = 3.0e38f, cr = 0.f, cg = 0.f, cb = 0.f;

    if (i < P) {
        float m0 = means3D[3 * i + 0];
        float m1 = means3D[3 * i + 1];
        float m2 = means3D[3 * i + 2];

        // p_view = m @ V[:3,:3] + V[3,:3]   (row-vector convention)
        float pv0 = m0 * vm[0] + m1 * vm[4] + m2 * vm[8]  + vm[12];
        float pv1 = m0 * vm[1] + m1 * vm[5] + m2 * vm[9]  + vm[13];
        float pv2 = m0 * vm[2] + m1 * vm[6] + m2 * vm[10] + vm[14];

        // p_hom = [m,1] @ P (4x4)
        float ph0 = m0 * pm[0] + m1 * pm[4] + m2 * pm[8]  + pm[12];
        float ph1 = m0 * pm[1] + m1 * pm[5] + m2 * pm[9]  + pm[13];
        float ph3 = m0 * pm[3] + m1 * pm[7] + m2 * pm[11] + pm[15];
        float pw = ph3 + 1e-7f;
        float ppx = ph0 / pw;
        float ppy = ph1 / pw;

        depth = pv2;
        bool in_frustum = depth > NEAR_Z;

        // quaternion -> rotation
        float q0 = rots[4 * i + 0], q1 = rots[4 * i + 1];
        float q2 = rots[4 * i + 2], q3 = rots[4 * i + 3];
        float qn = sqrtf(q0 * q0 + q1 * q1 + q2 * q2 + q3 * q3);
        q0 /= qn; q1 /= qn; q2 /= qn; q3 /= qn;
        float R00 = 1.f - 2.f * (q2 * q2 + q3 * q3);
        float R01 = 2.f * (q1 * q2 - q0 * q3);
        float R02 = 2.f * (q1 * q3 + q0 * q2);
        float R10 = 2.f * (q1 * q2 + q0 * q3);
        float R11 = 1.f - 2.f * (q1 * q1 + q3 * q3);
        float R12 = 2.f * (q2 * q3 - q0 * q1);
        float R20 = 2.f * (q1 * q3 - q0 * q2);
        float R21 = 2.f * (q2 * q3 + q0 * q1);
        float R22 = 1.f - 2.f * (q1 * q1 + q2 * q2);

        float s0 = SCALE_MOD * scales[3 * i + 0]; s0 = s0 * s0;
        float s1 = SCALE_MOD * scales[3 * i + 1]; s1 = s1 * s1;
        float s2v = SCALE_MOD * scales[3 * i + 2]; s2v = s2v * s2v;

        // Sigma = R diag(s2) R^T  (symmetric, 6 entries)
        float S00 = R00 * R00 * s0 + R01 * R01 * s1 + R02 * R02 * s2v;
        float S01 = R00 * R10 * s0 + R01 * R11 * s1 + R02 * R12 * s2v;
        float S02 = R00 * R20 * s0 + R01 * R21 * s1 + R02 * R22 * s2v;
        float S11 = R10 * R10 * s0 + R11 * R11 * s1 + R12 * R12 * s2v;
        float S12 = R10 * R20 * s0 + R11 * R21 * s1 + R12 * R22 * s2v;
        float S22 = R20 * R20 * s0 + R21 * R21 * s1 + R22 * R22 * s2v;

        float tz = in_frustum ? depth : 1.f;
        float lx = 1.3f * TANFOVX, ly = 1.3f * TANFOVY;
        float tx = fminf(fmaxf(pv0 / tz, -lx), lx) * tz;
        float ty = fminf(fmaxf(pv1 / tz, -ly), ly) * tz;
        const float fx = IMG_W / (2.0f * TANFOVX);
        const float fy = IMG_H / (2.0f * TANFOVY);
        float J00 = fx / tz, J02 = -fx * tx / (tz * tz);
        float J11 = fy / tz, J12 = -fy * ty / (tz * tz);

        // Tm = J @ V^T : Tm[a][c] = J[a][0]*V[c][0] + J[a][2]*V[c][2] (row a=0), etc.
        float T00 = J00 * vm[0]  + J02 * vm[2];
        float T01 = J00 * vm[4]  + J02 * vm[6];
        float T02 = J00 * vm[8]  + J02 * vm[10];
        float T10 = J11 * vm[1]  + J12 * vm[2];
        float T11 = J11 * vm[5]  + J12 * vm[6];
        float T12 = J11 * vm[9]  + J12 * vm[10];

        // cov2d = Tm Sigma Tm^T
        float a0 = S00 * T00 + S01 * T01 + S02 * T02;
        float a1 = S01 * T00 + S11 * T01 + S12 * T02;
        float a2 = S02 * T00 + S12 * T01 + S22 * T02;
        float b0 = S00 * T10 + S01 * T11 + S02 * T12;
        float b1 = S01 * T10 + S11 * T11 + S12 * T12;
        float b2 = S02 * T10 + S12 * T11 + S22 * T12;
        float cov00 = T00 * a0 + T01 * a1 + T02 * a2;
        float cov01 = T10 * a0 + T11 * a1 + T12 * a2;
        float cov11 = T10 * b0 + T11 * b1 + T12 * b2;

        float c00 = cov00 + 0.3f;
        float c11 = cov11 + 0.3f;
        float c01 = cov01;
        float det = c00 * c11 - c01 * c01;
        bool valid = in_frustum && (det > 0.f);
        float det_s = (det > 0.f) ? det : 1.f;
        conA = c11 / det_s;
        conB = -c01 / det_s;
        conC = c00 / det_s;

        float mid = 0.5f * (c00 + c11);
        float lam1 = mid + sqrtf(fmaxf(0.1f, mid * mid - det));
        int radii = valid ? (int)ceilf(3.0f * sqrtf(lam1)) : 0;

        pxp = ((ppx + 1.0f) * IMG_W - 1.0f) * 0.5f;
        pyp = ((ppy + 1.0f) * IMG_H - 1.0f) * 0.5f;

        op = opac[i];
        cr = colors[3 * i + 0];
        cg = colors[3 * i + 1];
        cb = colors[3 * i + 2];
        // contribute only when power >= log(ALPHA_MIN/op); slack covers fp jitter,
        // exact alpha test re-applied in render.
        thr = valid ? (logf(ALPHA_MIN / op) - 1e-3f) : 3.0e38f;

        out_radii[i] = (float)radii;  // radii returned in ORIGINAL order
    }

    s_depth[i] = depth;
    __syncthreads();

    if (i < P) {
        // stable rank (matches jnp.argsort)
        int rank = 0;
        for (int j = 0; j < P; j++) {
            float dj = s_depth[j];
            rank += (dj < depth) || (dj == depth && j < i);
        }
        g_px[rank] = pxp;  g_py[rank] = pyp;
        g_cA[rank] = conA; g_cB[rank] = conB; g_cC[rank] = conC;
        g_op[rank] = op;   g_thr[rank] = thr;
        g_cr[rank] = cr;   g_cg[rank] = cg;   g_cb[rank] = cb;
    }
}

__global__ void __launch_bounds__(256) render_kernel(const float* __restrict__ bg,
                                                     float* __restrict__ out,
                                                     int P) {
    __shared__ float s_px[PMAX], s_py[PMAX];
    __shared__ float s_cA[PMAX], s_cB[PMAX], s_cC[PMAX];
    __shared__ float s_op[PMAX], s_thr[PMAX];
    __shared__ float s_cr[PMAX], s_cg[PMAX], s_cb[PMAX];

    int tid = threadIdx.x;
    for (int j = tid; j < P; j += blockDim.x) {
        s_px[j] = g_px[j];   s_py[j] = g_py[j];
        s_cA[j] = g_cA[j];   s_cB[j] = g_cB[j];   s_cC[j] = g_cC[j];
        s_op[j] = g_op[j];   s_thr[j] = g_thr[j];
        s_cr[j] = g_cr[j];   s_cg[j] = g_cg[j];   s_cb[j] = g_cb[j];
    }
    __syncthreads();

    int pix = blockIdx.x * blockDim.x + tid;
    if (pix >= IMG_H * IMG_W) return;
    float xp = (float)(pix % IMG_W);
    float yp = (float)(pix / IMG_W);

    float T = 1.0f;
    float accr = 0.f, accg = 0.f, accb = 0.f;

    for (int j = 0; j < P; j++) {
        float dx = s_px[j] - xp;
        float dy = s_py[j] - yp;
        float power = -0.5f * (s_cA[j] * dx * dx + s_cC[j] * dy * dy) - s_cB[j] * dx * dy;
        float a = 0.f;
        if (power <= 0.f && power >= s_thr[j]) {
            float gval = expf(power);
            a = fminf(0.99f, s_op[j] * gval);
            if (a < ALPHA_MIN) a = 0.f;
        }
        float test = T * (1.0f - a);
        if (test < T_EPS) break;
        if (a > 0.f) {
            float w = a * T;
            accr += w * s_cr[j];
            accg += w * s_cg[j];
            accb += w * s_cb[j];
            T = test;
        }
    }

    const int HW = IMG_H * IMG_W;
    out[pix]          = accr + bg[0] * T;
    out[HW + pix]     = accg + bg[1] * T;
    out[2 * HW + pix] = accb + bg[2] * T;
}

extern "C" void kernel_launch(void* const* d_in, const int* in_sizes, int n_in,
                              void* d_out, int out_size) {
    const float* means3D = (const float*)d_in[0];
    // d_in[1] = means2D (unused by reference)
    const float* opac    = (const float*)d_in[2];
    const float* colors  = (const float*)d_in[3];
    const float* scales  = (const float*)d_in[4];
    const float* rots    = (const float*)d_in[5];
    const float* bg      = (const float*)d_in[6];
    const float* vm      = (const float*)d_in[7];
    const float* pm      = (const float*)d_in[8];
    float* out = (float*)d_out;

    int P = in_sizes[0] / 3;
    if (P > PMAX) P = PMAX;

    int nt = ((P + 31) / 32) * 32;
    if (nt < 32) nt = 32;
    preprocess_kernel<<<1, nt>>>(means3D, opac, colors, scales, rots, vm, pm,
                                 out + 3 * IMG_H * IMG_W, P);

    int npix = IMG_H * IMG_W;
    render_kernel<<<(npix + 255) / 256, 256>>>(bg, out, P);
}

// round 3
// speedup vs baseline: 2.9845x; 2.9845x over previous
#include <cuda_runtime.h>
#include <math.h>

#define IMG_H 192
#define IMG_W 192
#define TANFOVX 0.5f
#define TANFOVY 0.5f
#define SCALE_MOD 1.0f
#define NEAR_Z 0.2f
#define ALPHA_MIN (1.0f / 255.0f)
#define T_EPS 1.0e-4f
#define PMAX 256
#define TILE 16

// Sorted per-gaussian params (SoA float4), produced by preprocess, consumed by render.
__device__ float4 g_a[PMAX];   // px, py, conA, conB
__device__ float4 g_b[PMAX];   // conC, op, thr, (unused)
__device__ float4 g_c[PMAX];   // cr, cg, cb, (unused)
__device__ float4 g_bb[PMAX];  // xmin, xmax, ymin, ymax

__global__ void preprocess_kernel(const float* __restrict__ means3D,
                                  const float* __restrict__ opac,
                                  const float* __restrict__ colors,
                                  const float* __restrict__ scales,
                                  const float* __restrict__ rots,
                                  const float* __restrict__ vm,
                                  const float* __restrict__ pm,
                                  float* __restrict__ out_radii,
                                  int P) {
    int i = threadIdx.x;
    __shared__ float s_depth[PMAX];

    float depth = 3.4e38f;
    float pxp = 0.f, pyp = 0.f, conA = 0.f, conB = 0.f, conC = 0.f;
    float op = 0.f, thr = 3.0e38f, cr = 0.f, cg = 0.f, cb = 0.f;
    float ext_x = -1.f, ext_y = -1.f;

    if (i < P) {
        float m0 = means3D[3 * i + 0];
        float m1 = means3D[3 * i + 1];
        float m2 = means3D[3 * i + 2];

        // p_view = m @ V[:3,:3] + V[3,:3]   (row-vector convention)
        float pv0 = m0 * vm[0] + m1 * vm[4] + m2 * vm[8]  + vm[12];
        float pv1 = m0 * vm[1] + m1 * vm[5] + m2 * vm[9]  + vm[13];
        float pv2 = m0 * vm[2] + m1 * vm[6] + m2 * vm[10] + vm[14];

        // p_hom = [m,1] @ P (4x4)
        float ph0 = m0 * pm[0] + m1 * pm[4] + m2 * pm[8]  + pm[12];
        float ph1 = m0 * pm[1] + m1 * pm[5] + m2 * pm[9]  + pm[13];
        float ph3 = m0 * pm[3] + m1 * pm[7] + m2 * pm[11] + pm[15];
        float pw = ph3 + 1e-7f;
        float ppx = ph0 / pw;
        float ppy = ph1 / pw;

        depth = pv2;
        bool in_frustum = depth > NEAR_Z;

        // quaternion -> rotation
        float q0 = rots[4 * i + 0], q1 = rots[4 * i + 1];
        float q2 = rots[4 * i + 2], q3 = rots[4 * i + 3];
        float qn = sqrtf(q0 * q0 + q1 * q1 + q2 * q2 + q3 * q3);
        q0 /= qn; q1 /= qn; q2 /= qn; q3 /= qn;
        float R00 = 1.f - 2.f * (q2 * q2 + q3 * q3);
        float R01 = 2.f * (q1 * q2 - q0 * q3);
        float R02 = 2.f * (q1 * q3 + q0 * q2);
        float R10 = 2.f * (q1 * q2 + q0 * q3);
        float R11 = 1.f - 2.f * (q1 * q1 + q3 * q3);
        float R12 = 2.f * (q2 * q3 - q0 * q1);
        float R20 = 2.f * (q1 * q3 - q0 * q2);
        float R21 = 2.f * (q2 * q3 + q0 * q1);
        float R22 = 1.f - 2.f * (q1 * q1 + q2 * q2);

        float s0 = SCALE_MOD * scales[3 * i + 0]; s0 = s0 * s0;
        float s1 = SCALE_MOD * scales[3 * i + 1]; s1 = s1 * s1;
        float s2v = SCALE_MOD * scales[3 * i + 2]; s2v = s2v * s2v;

        // Sigma = R diag(s2) R^T  (symmetric)
        float S00 = R00 * R00 * s0 + R01 * R01 * s1 + R02 * R02 * s2v;
        float S01 = R00 * R10 * s0 + R01 * R11 * s1 + R02 * R12 * s2v;
        float S02 = R00 * R20 * s0 + R01 * R21 * s1 + R02 * R22 * s2v;
        float S11 = R10 * R10 * s0 + R11 * R11 * s1 + R12 * R12 * s2v;
        float S12 = R10 * R20 * s0 + R11 * R21 * s1 + R12 * R22 * s2v;
        float S22 = R20 * R20 * s0 + R21 * R21 * s1 + R22 * R22 * s2v;

        float tz = in_frustum ? depth : 1.f;
        float lx = 1.3f * TANFOVX, ly = 1.3f * TANFOVY;
        float tx = fminf(fmaxf(pv0 / tz, -lx), lx) * tz;
        float ty = fminf(fmaxf(pv1 / tz, -ly), ly) * tz;
        const float fx = IMG_W / (2.0f * TANFOVX);
        const float fy = IMG_H / (2.0f * TANFOVY);
        float J00 = fx / tz, J02 = -fx * tx / (tz * tz);
        float J11 = fy / tz, J12 = -fy * ty / (tz * tz);

        // Tm = J @ V^T
        float T00 = J00 * vm[0]  + J02 * vm[2];
        float T01 = J00 * vm[4]  + J02 * vm[6];
        float T02 = J00 * vm[8]  + J02 * vm[10];
        float T10 = J11 * vm[1]  + J12 * vm[2];
        float T11 = J11 * vm[5]  + J12 * vm[6];
        float T12 = J11 * vm[9]  + J12 * vm[10];

        // cov2d = Tm Sigma Tm^T
        float a0 = S00 * T00 + S01 * T01 + S02 * T02;
        float a1 = S01 * T00 + S11 * T01 + S12 * T02;
        float a2 = S02 * T00 + S12 * T01 + S22 * T02;
        float b0 = S00 * T10 + S01 * T11 + S02 * T12;
        float b1 = S01 * T10 + S11 * T11 + S12 * T12;
        float b2 = S02 * T10 + S12 * T11 + S22 * T12;
        float cov00 = T00 * a0 + T01 * a1 + T02 * a2;
        float cov01 = T10 * a0 + T11 * a1 + T12 * a2;
        float cov11 = T10 * b0 + T11 * b1 + T12 * b2;

        float c00 = cov00 + 0.3f;
        float c11 = cov11 + 0.3f;
        float c01 = cov01;
        float det = c00 * c11 - c01 * c01;
        bool valid = in_frustum && (det > 0.f);
        float det_s = (det > 0.f) ? det : 1.f;
        conA = c11 / det_s;
        conB = -c01 / det_s;
        conC = c00 / det_s;

        float mid = 0.5f * (c00 + c11);
        float lam1 = mid + sqrtf(fmaxf(0.1f, mid * mid - det));
        int radii = valid ? (int)ceilf(3.0f * sqrtf(lam1)) : 0;

        pxp = ((ppx + 1.0f) * IMG_W - 1.0f) * 0.5f;
        pyp = ((ppy + 1.0f) * IMG_H - 1.0f) * 0.5f;

        op = opac[i];
        cr = colors[3 * i + 0];
        cg = colors[3 * i + 1];
        cb = colors[3 * i + 2];
        // contribute only when power >= log(ALPHA_MIN/op); slack covers fp jitter,
        // exact alpha test re-applied in render.
        thr = valid ? (logf(ALPHA_MIN / op) - 1e-3f) : 3.0e38f;

        if (valid && thr < 0.f) {
            // level set power == thr has max |dx| = sqrt(-2*thr*c00) (conic^-1 = cov)
            ext_x = sqrtf(-2.f * thr * c00) + 1.0f;  // +1px safety margin
            ext_y = sqrtf(-2.f * thr * c11) + 1.0f;
        }

        out_radii[i] = (float)radii;  // radii returned in ORIGINAL order
    }

    s_depth[i] = depth;
    __syncthreads();

    if (i < P) {
        // stable rank (matches jnp.argsort)
        int rank = 0;
        for (int j = 0; j < P; j++) {
            float dj = s_depth[j];
            rank += (dj < depth) || (dj == depth && j < i);
        }
        g_a[rank] = make_float4(pxp, pyp, conA, conB);
        g_b[rank] = make_float4(conC, op, thr, 0.f);
        g_c[rank] = make_float4(cr, cg, cb, 0.f);
        if (ext_x > 0.f) {
            g_bb[rank] = make_float4(pxp - ext_x, pxp + ext_x, pyp - ext_y, pyp + ext_y);
        } else {
            g_bb[rank] = make_float4(1e9f, -1e9f, 1e9f, -1e9f);  // empty
        }
    }
}

__global__ void __launch_bounds__(256) render_kernel(const float* __restrict__ bg,
                                                     float* __restrict__ out,
                                                     int P) {
    __shared__ float4 s_a[PMAX];
    __shared__ float4 s_b[PMAX];
    __shared__ float4 s_c[PMAX];
    __shared__ int s_woff[8];
    __shared__ int s_n;

    const int tid = threadIdx.x;
    const int tiles_x = IMG_W / TILE;
    const int tile_x = blockIdx.x % tiles_x;
    const int tile_y = blockIdx.x / tiles_x;
    const float tx0 = (float)(tile_x * TILE) - 0.5f;
    const float tx1 = (float)(tile_x * TILE + TILE - 1) + 0.5f;
    const float ty0 = (float)(tile_y * TILE) - 0.5f;
    const float ty1 = (float)(tile_y * TILE + TILE - 1) + 0.5f;

    // ---- order-preserving compaction of gaussians overlapping this tile ----
    bool pred = false;
    if (tid < P) {
        float4 bb = g_bb[tid];  // xmin,xmax,ymin,ymax
        pred = (bb.x <= tx1) && (bb.y >= tx0) && (bb.z <= ty1) && (bb.w >= ty0);
    }
    unsigned m = __ballot_sync(0xffffffffu, pred);
    int lane = tid & 31, wid = tid >> 5;
    if (lane == 0) s_woff[wid] = __popc(m);
    __syncthreads();
    if (tid == 0) {
        int s = 0;
        #pragma unroll
        for (int w = 0; w < 8; w++) { int c = s_woff[w]; s_woff[w] = s; s += c; }
        s_n = s;
    }
    __syncthreads();
    if (pred) {
        int pos = s_woff[wid] + __popc(m & ((1u << lane) - 1u));
        s_a[pos] = g_a[tid];
        s_b[pos] = g_b[tid];
        s_c[pos] = g_c[tid];
    }
    __syncthreads();
    const int n = s_n;

    // ---- per-pixel front-to-back composite over the compacted list ----
    const int px_i = tile_x * TILE + (tid & (TILE - 1));
    const int py_i = tile_y * TILE + (tid >> 4);
    const float xp = (float)px_i;
    const float yp = (float)py_i;

    float T = 1.0f;
    float accr = 0.f, accg = 0.f, accb = 0.f;

    for (int j = 0; j < n; j++) {
        float4 ga = s_a[j];  // px,py,cA,cB
        float4 gb = s_b[j];  // cC,op,thr
        float dx = ga.x - xp;
        float dy = ga.y - yp;
        float power = fmaf(-0.5f * ga.z, dx * dx,
                      fmaf(-0.5f * gb.x, dy * dy, -ga.w * (dx * dy)));
        float a = 0.f;
        if (power <= 0.f && power >= gb.z) {
            a = fminf(0.99f, gb.y * __expf(power));
            if (a < ALPHA_MIN) a = 0.f;
        }
        float test = T * (1.0f - a);
        if (test < T_EPS) break;
        if (a > 0.f) {
            float4 gc = s_c[j];
            float w = a * T;
            accr = fmaf(w, gc.x, accr);
            accg = fmaf(w, gc.y, accg);
            accb = fmaf(w, gc.z, accb);
            T = test;
        }
    }

    const int HW = IMG_H * IMG_W;
    const int pix = py_i * IMG_W + px_i;
    out[pix]          = accr + bg[0] * T;
    out[HW + pix]     = accg + bg[1] * T;
    out[2 * HW + pix] = accb + bg[2] * T;
}

extern "C" void kernel_launch(void* const* d_in, const int* in_sizes, int n_in,
                              void* d_out, int out_size) {
    const float* means3D = (const float*)d_in[0];
    // d_in[1] = means2D (unused by reference)
    const float* opac    = (const float*)d_in[2];
    const float* colors  = (const float*)d_in[3];
    const float* scales  = (const float*)d_in[4];
    const float* rots    = (const float*)d_in[5];
    const float* bg      = (const float*)d_in[6];
    const float* vm      = (const float*)d_in[7];
    const float* pm      = (const float*)d_in[8];
    float* out = (float*)d_out;

    int P = in_sizes[0] / 3;
    if (P > PMAX) P = PMAX;

    int nt = ((P + 31) / 32) * 32;
    if (nt < 32) nt = 32;
    preprocess_kernel<<<1, nt>>>(means3D, opac, colors, scales, rots, vm, pm,
                                 out + 3 * IMG_H * IMG_W, P);

    const int tiles = (IMG_W / TILE) * (IMG_H / TILE);
    render_kernel<<<tiles, TILE * TILE>>>(bg, out, P);
}

// round 4
// speedup vs baseline: 3.2285x; 1.0818x over previous
#include <cuda_runtime.h>
#include <math.h>

#define IMG_H 192
#define IMG_W 192
#define TANFOVX 0.5f
#define TANFOVY 0.5f
#define SCALE_MOD 1.0f
#define NEAR_Z 0.2f
#define ALPHA_MIN (1.0f / 255.0f)
#define T_EPS 1.0e-4f
#define PMAX 256
#define TILE 16

// Single fused kernel: every block redundantly preprocesses all P gaussians
// (thread t -> gaussian t), rank-sorts by depth into shared SoA, tile-culls,
// then composites its 16x16 pixel tile. No global scratch, one launch.
__global__ void __launch_bounds__(256) fused_kernel(const float* __restrict__ means3D,
                                                    const float* __restrict__ opac,
                                                    const float* __restrict__ colors,
                                                    const float* __restrict__ scales,
                                                    const float* __restrict__ rots,
                                                    const float* __restrict__ vm,
                                                    const float* __restrict__ pm,
                                                    const float* __restrict__ bg,
                                                    float* __restrict__ out,
                                                    int P) {
    __shared__ float  s_depth[PMAX];
    __shared__ float4 s_a[PMAX];   // px, py, conA, conB   (depth-sorted)
    __shared__ float4 s_b[PMAX];   // conC, op, thr
    __shared__ float4 s_c[PMAX];   // cr, cg, cb
    __shared__ float4 s_bb[PMAX];  // xmin, xmax, ymin, ymax
    __shared__ int    s_idx[PMAX]; // compacted sorted indices for this tile
    __shared__ int    s_woff[8];
    __shared__ int    s_n;

    const int tid = threadIdx.x;
    const int i = tid;

    // ---------------- per-gaussian preprocess (thread i -> gaussian i) ------
    float depth = 3.4e38f;
    float pxp = 0.f, pyp = 0.f, conA = 0.f, conB = 0.f, conC = 0.f;
    float op = 0.f, thr = 3.0e38f, cr = 0.f, cg = 0.f, cb = 0.f;
    float ext_x = -1.f, ext_y = -1.f;
    int radii = 0;

    if (i < P) {
        float m0 = means3D[3 * i + 0];
        float m1 = means3D[3 * i + 1];
        float m2 = means3D[3 * i + 2];

        // p_view = m @ V[:3,:3] + V[3,:3]   (row-vector convention)
        float pv0 = m0 * vm[0] + m1 * vm[4] + m2 * vm[8]  + vm[12];
        float pv1 = m0 * vm[1] + m1 * vm[5] + m2 * vm[9]  + vm[13];
        float pv2 = m0 * vm[2] + m1 * vm[6] + m2 * vm[10] + vm[14];

        // p_hom = [m,1] @ P (4x4)
        float ph0 = m0 * pm[0] + m1 * pm[4] + m2 * pm[8]  + pm[12];
        float ph1 = m0 * pm[1] + m1 * pm[5] + m2 * pm[9]  + pm[13];
        float ph3 = m0 * pm[3] + m1 * pm[7] + m2 * pm[11] + pm[15];
        float pw = ph3 + 1e-7f;
        float ppx = ph0 / pw;
        float ppy = ph1 / pw;

        depth = pv2;
        bool in_frustum = depth > NEAR_Z;

        // quaternion -> rotation
        float q0 = rots[4 * i + 0], q1 = rots[4 * i + 1];
        float q2 = rots[4 * i + 2], q3 = rots[4 * i + 3];
        float qn = sqrtf(q0 * q0 + q1 * q1 + q2 * q2 + q3 * q3);
        q0 /= qn; q1 /= qn; q2 /= qn; q3 /= qn;
        float R00 = 1.f - 2.f * (q2 * q2 + q3 * q3);
        float R01 = 2.f * (q1 * q2 - q0 * q3);
        float R02 = 2.f * (q1 * q3 + q0 * q2);
        float R10 = 2.f * (q1 * q2 + q0 * q3);
        float R11 = 1.f - 2.f * (q1 * q1 + q3 * q3);
        float R12 = 2.f * (q2 * q3 - q0 * q1);
        float R20 = 2.f * (q1 * q3 - q0 * q2);
        float R21 = 2.f * (q2 * q3 + q0 * q1);
        float R22 = 1.f - 2.f * (q1 * q1 + q2 * q2);

        float s0 = SCALE_MOD * scales[3 * i + 0]; s0 = s0 * s0;
        float s1 = SCALE_MOD * scales[3 * i + 1]; s1 = s1 * s1;
        float s2v = SCALE_MOD * scales[3 * i + 2]; s2v = s2v * s2v;

        // Sigma = R diag(s2) R^T  (symmetric)
        float S00 = R00 * R00 * s0 + R01 * R01 * s1 + R02 * R02 * s2v;
        float S01 = R00 * R10 * s0 + R01 * R11 * s1 + R02 * R12 * s2v;
        float S02 = R00 * R20 * s0 + R01 * R21 * s1 + R02 * R22 * s2v;
        float S11 = R10 * R10 * s0 + R11 * R11 * s1 + R12 * R12 * s2v;
        float S12 = R10 * R20 * s0 + R11 * R21 * s1 + R12 * R22 * s2v;
        float S22 = R20 * R20 * s0 + R21 * R21 * s1 + R22 * R22 * s2v;

        float tz = in_frustum ? depth : 1.f;
        float lx = 1.3f * TANFOVX, ly = 1.3f * TANFOVY;
        float tx = fminf(fmaxf(pv0 / tz, -lx), lx) * tz;
        float ty = fminf(fmaxf(pv1 / tz, -ly), ly) * tz;
        const float fx = IMG_W / (2.0f * TANFOVX);
        const float fy = IMG_H / (2.0f * TANFOVY);
        float J00 = fx / tz, J02 = -fx * tx / (tz * tz);
        float J11 = fy / tz, J12 = -fy * ty / (tz * tz);

        // Tm = J @ V^T
        float T00 = J00 * vm[0]  + J02 * vm[2];
        float T01 = J00 * vm[4]  + J02 * vm[6];
        float T02 = J00 * vm[8]  + J02 * vm[10];
        float T10 = J11 * vm[1]  + J12 * vm[2];
        float T11 = J11 * vm[5]  + J12 * vm[6];
        float T12 = J11 * vm[9]  + J12 * vm[10];

        // cov2d = Tm Sigma Tm^T
        float a0 = S00 * T00 + S01 * T01 + S02 * T02;
        float a1 = S01 * T00 + S11 * T01 + S12 * T02;
        float a2 = S02 * T00 + S12 * T01 + S22 * T02;
        float b0 = S00 * T10 + S01 * T11 + S02 * T12;
        float b1 = S01 * T10 + S11 * T11 + S12 * T12;
        float b2 = S02 * T10 + S12 * T11 + S22 * T12;
        float cov00 = T00 * a0 + T01 * a1 + T02 * a2;
        float cov01 = T10 * a0 + T11 * a1 + T12 * a2;
        float cov11 = T10 * b0 + T11 * b1 + T12 * b2;

        float c00 = cov00 + 0.3f;
        float c11 = cov11 + 0.3f;
        float c01 = cov01;
        float det = c00 * c11 - c01 * c01;
        bool valid = in_frustum && (det > 0.f);
        float det_s = (det > 0.f) ? det : 1.f;
        conA = c11 / det_s;
        conB = -c01 / det_s;
        conC = c00 / det_s;

        float mid = 0.5f * (c00 + c11);
        float lam1 = mid + sqrtf(fmaxf(0.1f, mid * mid - det));
        radii = valid ? (int)ceilf(3.0f * sqrtf(lam1)) : 0;

        pxp = ((ppx + 1.0f) * IMG_W - 1.0f) * 0.5f;
        pyp = ((ppy + 1.0f) * IMG_H - 1.0f) * 0.5f;

        op = opac[i];
        cr = colors[3 * i + 0];
        cg = colors[3 * i + 1];
        cb = colors[3 * i + 2];
        // contribute only when power >= log(ALPHA_MIN/op); slack covers fp jitter,
        // exact alpha test re-applied in composite.
        thr = valid ? (logf(ALPHA_MIN / op) - 1e-3f) : 3.0e38f;

        if (valid && thr < 0.f) {
            // level set power == thr has max |dx| = sqrt(-2*thr*c00) (conic^-1 = cov)
            ext_x = sqrtf(-2.f * thr * c00) + 1.0f;  // +1px safety margin
            ext_y = sqrtf(-2.f * thr * c11) + 1.0f;
        }

        if (blockIdx.x == 0) out[3 * IMG_H * IMG_W + i] = (float)radii;
    }

    s_depth[tid] = depth;
    __syncthreads();

    // ---------------- stable rank-sort by depth into shared SoA -------------
    if (i < P) {
        int rank = 0;
        #pragma unroll 4
        for (int j = 0; j < P; j++) {
            float dj = s_depth[j];
            rank += (dj < depth) || (dj == depth && j < i);
        }
        s_a[rank] = make_float4(pxp, pyp, conA, conB);
        s_b[rank] = make_float4(conC, op, thr, 0.f);
        s_c[rank] = make_float4(cr, cg, cb, 0.f);
        if (ext_x > 0.f) {
            s_bb[rank] = make_float4(pxp - ext_x, pxp + ext_x, pyp - ext_y, pyp + ext_y);
        } else {
            s_bb[rank] = make_float4(1e9f, -1e9f, 1e9f, -1e9f);  // empty
        }
    }
    __syncthreads();

    // ---------------- tile cull: compact sorted indices overlapping tile ----
    const int tiles_x = IMG_W / TILE;
    const int tile_x = blockIdx.x % tiles_x;
    const int tile_y = blockIdx.x / tiles_x;
    const float tx0 = (float)(tile_x * TILE) - 0.5f;
    const float tx1 = (float)(tile_x * TILE + TILE - 1) + 0.5f;
    const float ty0 = (float)(tile_y * TILE) - 0.5f;
    const float ty1 = (float)(tile_y * TILE + TILE - 1) + 0.5f;

    bool pred = false;
    if (tid < P) {
        float4 bb = s_bb[tid];
        pred = (bb.x <= tx1) && (bb.y >= tx0) && (bb.z <= ty1) && (bb.w >= ty0);
    }
    unsigned m = __ballot_sync(0xffffffffu, pred);
    int lane = tid & 31, wid = tid >> 5;
    if (lane == 0) s_woff[wid] = __popc(m);
    __syncthreads();
    if (tid == 0) {
        int s = 0;
        #pragma unroll
        for (int w = 0; w < 8; w++) { int c = s_woff[w]; s_woff[w] = s; s += c; }
        s_n = s;
    }
    __syncthreads();
    if (pred) {
        int pos = s_woff[wid] + __popc(m & ((1u << lane) - 1u));
        s_idx[pos] = tid;
    }
    __syncthreads();
    const int n = s_n;

    // ---------------- per-pixel front-to-back composite ---------------------
    const int px_i = tile_x * TILE + (tid & (TILE - 1));
    const int py_i = tile_y * TILE + (tid >> 4);
    const float xp = (float)px_i;
    const float yp = (float)py_i;

    float T = 1.0f;
    float accr = 0.f, accg = 0.f, accb = 0.f;

    for (int j = 0; j < n; j++) {
        int idx = s_idx[j];          // broadcast
        float4 ga = s_a[idx];        // px,py,cA,cB (broadcast)
        float4 gb = s_b[idx];        // cC,op,thr
        float dx = ga.x - xp;
        float dy = ga.y - yp;
        float power = fmaf(-0.5f * ga.z, dx * dx,
                      fmaf(-0.5f * gb.x, dy * dy, -ga.w * (dx * dy)));
        float a = 0.f;
        if (power <= 0.f && power >= gb.z) {
            a = fminf(0.99f, gb.y * __expf(power));
            if (a < ALPHA_MIN) a = 0.f;
        }
        float test = T * (1.0f - a);
        if (test < T_EPS) break;
        if (a > 0.f) {
            float4 gc = s_c[idx];
            float w = a * T;
            accr = fmaf(w, gc.x, accr);
            accg = fmaf(w, gc.y, accg);
            accb = fmaf(w, gc.z, accb);
            T = test;
        }
    }

    const int HW = IMG_H * IMG_W;
    const int pix = py_i * IMG_W + px_i;
    out[pix]          = accr + bg[0] * T;
    out[HW + pix]     = accg + bg[1] * T;
    out[2 * HW + pix] = accb + bg[2] * T;
}

extern "C" void kernel_launch(void* const* d_in, const int* in_sizes, int n_in,
                              void* d_out, int out_size) {
    const float* means3D = (const float*)d_in[0];
    // d_in[1] = means2D (unused by reference)
    const float* opac    = (const float*)d_in[2];
    const float* colors  = (const float*)d_in[3];
    const float* scales  = (const float*)d_in[4];
    const float* rots    = (const float*)d_in[5];
    const float* bg      = (const float*)d_in[6];
    const float* vm      = (const float*)d_in[7];
    const float* pm      = (const float*)d_in[8];
    float* out = (float*)d_out;

    int P = in_sizes[0] / 3;
    if (P > PMAX) P = PMAX;

    const int tiles = (IMG_W / TILE) * (IMG_H / TILE);
    fused_kernel<<<tiles, TILE * TILE>>>(means3D, opac, colors, scales, rots,
                                         vm, pm, bg, out, P);
}

// round 5
// speedup vs baseline: 4.7975x; 1.4860x over previous
#include <cuda_runtime.h>
#include <math.h>

#define IMG_H 192
#define IMG_W 192
#define TANFOVX 0.5f
#define TANFOVY 0.5f
#define SCALE_MOD 1.0f
#define NEAR_Z 0.2f
#define ALPHA_MIN (1.0f / 255.0f)
#define T_EPS 1.0e-4f
#define PMAX 256
#define TILE 16

// Single fused kernel: each block preprocesses all P gaussians (thread t ->
// gaussian t, params stay in registers), culls against its 16x16 tile, sorts
// only the survivors by depth, then composites. One launch, no global scratch.
__global__ void __launch_bounds__(256) fused_kernel(const float* __restrict__ means3D,
                                                    const float* __restrict__ opac,
                                                    const float* __restrict__ colors,
                                                    const float* __restrict__ scales,
                                                    const float* __restrict__ rots,
                                                    const float* __restrict__ vm,
                                                    const float* __restrict__ pm,
                                                    const float* __restrict__ bg,
                                                    float* __restrict__ out,
                                                    int P) {
    __shared__ float4 s_a[PMAX];   // px, py, -0.5*conA, -conB   (original index)
    __shared__ float4 s_b[PMAX];   // -0.5*conC, op, thr, depth
    __shared__ float4 s_c[PMAX];   // cr, cg, cb
    __shared__ int    s_surv[PMAX]; // survivor original indices (index order)
    __shared__ int    s_ord[PMAX];  // survivor original indices (depth order)
    __shared__ int    s_woff[8];
    __shared__ int    s_n;

    const int tid = threadIdx.x;
    const int i = tid;

    const int tiles_x = IMG_W / TILE;
    const int tile_x = blockIdx.x % tiles_x;
    const int tile_y = blockIdx.x / tiles_x;
    const float tx0 = (float)(tile_x * TILE) - 0.5f;
    const float tx1 = (float)(tile_x * TILE + TILE - 1) + 0.5f;
    const float ty0 = (float)(tile_y * TILE) - 0.5f;
    const float ty1 = (float)(tile_y * TILE + TILE - 1) + 0.5f;

    // ---------------- per-gaussian preprocess (thread i -> gaussian i) ------
    bool pred = false;
    if (i < P) {
        float m0 = means3D[3 * i + 0];
        float m1 = means3D[3 * i + 1];
        float m2 = means3D[3 * i + 2];

        // p_view = m @ V[:3,:3] + V[3,:3]   (row-vector convention)
        float pv0 = m0 * vm[0] + m1 * vm[4] + m2 * vm[8]  + vm[12];
        float pv1 = m0 * vm[1] + m1 * vm[5] + m2 * vm[9]  + vm[13];
        float pv2 = m0 * vm[2] + m1 * vm[6] + m2 * vm[10] + vm[14];

        // p_hom = [m,1] @ P (4x4)
        float ph0 = m0 * pm[0] + m1 * pm[4] + m2 * pm[8]  + pm[12];
        float ph1 = m0 * pm[1] + m1 * pm[5] + m2 * pm[9]  + pm[13];
        float ph3 = m0 * pm[3] + m1 * pm[7] + m2 * pm[11] + pm[15];
        float pwinv = __fdividef(1.f, ph3 + 1e-7f);
        float ppx = ph0 * pwinv;
        float ppy = ph1 * pwinv;

        float depth = pv2;
        bool in_frustum = depth > NEAR_Z;

        // quaternion -> rotation (normalize via rsqrt)
        float q0 = rots[4 * i + 0], q1 = rots[4 * i + 1];
        float q2 = rots[4 * i + 2], q3 = rots[4 * i + 3];
        float qinv = rsqrtf(q0 * q0 + q1 * q1 + q2 * q2 + q3 * q3);
        q0 *= qinv; q1 *= qinv; q2 *= qinv; q3 *= qinv;
        float R00 = 1.f - 2.f * (q2 * q2 + q3 * q3);
        float R01 = 2.f * (q1 * q2 - q0 * q3);
        float R02 = 2.f * (q1 * q3 + q0 * q2);
        float R10 = 2.f * (q1 * q2 + q0 * q3);
        float R11 = 1.f - 2.f * (q1 * q1 + q3 * q3);
        float R12 = 2.f * (q2 * q3 - q0 * q1);
        float R20 = 2.f * (q1 * q3 - q0 * q2);
        float R21 = 2.f * (q2 * q3 + q0 * q1);
        float R22 = 1.f - 2.f * (q1 * q1 + q2 * q2);

        float s0 = SCALE_MOD * scales[3 * i + 0]; s0 = s0 * s0;
        float s1 = SCALE_MOD * scales[3 * i + 1]; s1 = s1 * s1;
        float s2v = SCALE_MOD * scales[3 * i + 2]; s2v = s2v * s2v;

        // Sigma = R diag(s2) R^T  (symmetric)
        float S00 = R00 * R00 * s0 + R01 * R01 * s1 + R02 * R02 * s2v;
        float S01 = R00 * R10 * s0 + R01 * R11 * s1 + R02 * R12 * s2v;
        float S02 = R00 * R20 * s0 + R01 * R21 * s1 + R02 * R22 * s2v;
        float S11 = R10 * R10 * s0 + R11 * R11 * s1 + R12 * R12 * s2v;
        float S12 = R10 * R20 * s0 + R11 * R21 * s1 + R12 * R22 * s2v;
        float S22 = R20 * R20 * s0 + R21 * R21 * s1 + R22 * R22 * s2v;

        float tz = in_frustum ? depth : 1.f;
        float tzinv = __fdividef(1.f, tz);
        float lx = 1.3f * TANFOVX, ly = 1.3f * TANFOVY;
        float tx = fminf(fmaxf(pv0 * tzinv, -lx), lx) * tz;
        float ty = fminf(fmaxf(pv1 * tzinv, -ly), ly) * tz;
        const float fx = IMG_W / (2.0f * TANFOVX);
        const float fy = IMG_H / (2.0f * TANFOVY);
        float J00 = fx * tzinv, J02 = -fx * tx * tzinv * tzinv;
        float J11 = fy * tzinv, J12 = -fy * ty * tzinv * tzinv;

        // Tm = J @ V^T
        float T00 = J00 * vm[0]  + J02 * vm[2];
        float T01 = J00 * vm[4]  + J02 * vm[6];
        float T02 = J00 * vm[8]  + J02 * vm[10];
        float T10 = J11 * vm[1]  + J12 * vm[2];
        float T11 = J11 * vm[5]  + J12 * vm[6];
        float T12 = J11 * vm[9]  + J12 * vm[10];

        // cov2d = Tm Sigma Tm^T
        float a0 = S00 * T00 + S01 * T01 + S02 * T02;
        float a1 = S01 * T00 + S11 * T01 + S12 * T02;
        float a2 = S02 * T00 + S12 * T01 + S22 * T02;
        float b0 = S00 * T10 + S01 * T11 + S02 * T12;
        float b1 = S01 * T10 + S11 * T11 + S12 * T12;
        float b2 = S02 * T10 + S12 * T11 + S22 * T12;
        float cov00 = T00 * a0 + T01 * a1 + T02 * a2;
        float cov01 = T10 * a0 + T11 * a1 + T12 * a2;
        float cov11 = T10 * b0 + T11 * b1 + T12 * b2;

        float c00 = cov00 + 0.3f;
        float c11 = cov11 + 0.3f;
        float c01 = cov01;
        float det = c00 * c11 - c01 * c01;
        bool valid = in_frustum && (det > 0.f);
        float detinv = __fdividef(1.f, (det > 0.f) ? det : 1.f);
        float conA = c11 * detinv;
        float conB = -c01 * detinv;
        float conC = c00 * detinv;

        float mid = 0.5f * (c00 + c11);
        float lam1 = mid + sqrtf(fmaxf(0.1f, mid * mid - det));
        int radii = valid ? (int)ceilf(3.0f * sqrtf(lam1)) : 0;

        float pxp = ((ppx + 1.0f) * IMG_W - 1.0f) * 0.5f;
        float pyp = ((ppy + 1.0f) * IMG_H - 1.0f) * 0.5f;

        float op = opac[i];
        // contribute only when power >= log(ALPHA_MIN/op); slack covers fp jitter,
        // exact alpha test re-applied in composite.
        float thr = valid ? (__logf(__fdividef(ALPHA_MIN, op)) - 1e-3f) : 3.0e38f;

        if (valid && thr < 0.f) {
            // level set power == thr has max |dx| = sqrt(-2*thr*c00) (conic^-1 = cov)
            float ext_x = sqrtf(-2.f * thr * c00) + 1.0f;  // +1px safety margin
            float ext_y = sqrtf(-2.f * thr * c11) + 1.0f;
            pred = (pxp - ext_x <= tx1) && (pxp + ext_x >= tx0) &&
                   (pyp - ext_y <= ty1) && (pyp + ext_y >= ty0);
        }

        // -0.5*x and -x are exact; power arithmetic below is bit-identical to R4.
        s_a[i] = make_float4(pxp, pyp, -0.5f * conA, -conB);
        s_b[i] = make_float4(-0.5f * conC, op, thr, depth);
        s_c[i] = make_float4(colors[3 * i + 0], colors[3 * i + 1], colors[3 * i + 2], 0.f);

        if (blockIdx.x == 0) out[3 * IMG_H * IMG_W + i] = (float)radii;
    }

    // ---------------- compact survivor indices (original order) -------------
    unsigned m = __ballot_sync(0xffffffffu, pred);
    int lane = tid & 31, wid = tid >> 5;
    if (lane == 0) s_woff[wid] = __popc(m);
    __syncthreads();
    if (tid == 0) {
        int s = 0;
        #pragma unroll
        for (int w = 0; w < 8; w++) { int c = s_woff[w]; s_woff[w] = s; s += c; }
        s_n = s;
    }
    __syncthreads();
    if (pred) {
        int pos = s_woff[wid] + __popc(m & ((1u << lane) - 1u));
        s_surv[pos] = tid;
    }
    __syncthreads();
    const int n = s_n;

    // ---------------- stable depth rank among survivors only ----------------
    if (tid < n) {
        int my = s_surv[tid];
        float myd = s_b[my].w;
        int rank = 0;
        #pragma unroll 4
        for (int k = 0; k < n; k++) {
            int ok = s_surv[k];
            float dk = s_b[ok].w;
            rank += (dk < myd) || (dk == myd && ok < my);
        }
        s_ord[rank] = my;
    }
    __syncthreads();

    // ---------------- per-pixel front-to-back composite ---------------------
    const int px_i = tile_x * TILE + (tid & (TILE - 1));
    const int py_i = tile_y * TILE + (tid >> 4);
    const float xp = (float)px_i;
    const float yp = (float)py_i;

    float T = 1.0f;
    float accr = 0.f, accg = 0.f, accb = 0.f;
    bool done = false;

    int j = 0;
    for (; j + 4 <= n; j += 4) {
        #pragma unroll
        for (int u = 0; u < 4; u++) {
            int idx = s_ord[j + u];
            float4 ga = s_a[idx];  // px,py,nA,nB
            float4 gb = s_b[idx];  // nC,op,thr
            float dx = ga.x - xp;
            float dy = ga.y - yp;
            float power = fmaf(ga.z, dx * dx, fmaf(gb.x, dy * dy, ga.w * (dx * dy)));
            float a = 0.f;
            if (power <= 0.f && power >= gb.z) {
                a = fminf(0.99f, gb.y * __expf(power));
                if (a < ALPHA_MIN) a = 0.f;
            }
            float test = T * (1.0f - a);
            bool act = !done && (test >= T_EPS);
            done = done || (test < T_EPS);
            if (act & (a > 0.f)) {
                float4 gc = s_c[idx];
                float w = a * T;
                accr = fmaf(w, gc.x, accr);
                accg = fmaf(w, gc.y, accg);
                accb = fmaf(w, gc.z, accb);
                T = test;
            }
        }
        if (done) break;
    }
    if (!done) {
        for (; j < n; j++) {
            int idx = s_ord[j];
            float4 ga = s_a[idx];
            float4 gb = s_b[idx];
            float dx = ga.x - xp;
            float dy = ga.y - yp;
            float power = fmaf(ga.z, dx * dx, fmaf(gb.x, dy * dy, ga.w * (dx * dy)));
            float a = 0.f;
            if (power <= 0.f && power >= gb.z) {
                a = fminf(0.99f, gb.y * __expf(power));
                if (a < ALPHA_MIN) a = 0.f;
            }
            float test = T * (1.0f - a);
            bool act = !done && (test >= T_EPS);
            done = done || (test < T_EPS);
            if (act & (a > 0.f)) {
                float4 gc = s_c[idx];
                float w = a * T;
                accr = fmaf(w, gc.x, accr);
                accg = fmaf(w, gc.y, accg);
                accb = fmaf(w, gc.z, accb);
                T = test;
            }
        }
    }

    const int HW = IMG_H * IMG_W;
    const int pix = py_i * IMG_W + px_i;
    out[pix]          = accr + bg[0] * T;
    out[HW + pix]     = accg + bg[1] * T;
    out[2 * HW + pix] = accb + bg[2] * T;
}

extern "C" void kernel_launch(void* const* d_in, const int* in_sizes, int n_in,
                              void* d_out, int out_size) {
    const float* means3D = (const float*)d_in[0];
    // d_in[1] = means2D (unused by reference)
    const float* opac    = (const float*)d_in[2];
    const float* colors  = (const float*)d_in[3];
    const float* scales  = (const float*)d_in[4];
    const float* rots    = (const float*)d_in[5];
    const float* bg      = (const float*)d_in[6];
    const float* vm      = (const float*)d_in[7];
    const float* pm      = (const float*)d_in[8];
    float* out = (float*)d_out;

    int P = in_sizes[0] / 3;
    if (P > PMAX) P = PMAX;

    const int tiles = (IMG_W / TILE) * (IMG_H / TILE);
    fused_kernel<<<tiles, TILE * TILE>>>(means3D, opac, colors, scales, rots,
                                         vm, pm, bg, out, P);
}